// round 1
// baseline (speedup 1.0000x reference)
#include <cuda_runtime.h>
#include <cuda_bf16.h>
#include <math.h>

// Problem dims
#define BATCH 32
#define LEN   2048
#define DIM   1024
#define M_TOT (BATCH * LEN)        // 65536
#define NCHUNKS 8                  // DIM / BN

// GEMM tiling for the fused score kernel
#define BM 128
#define BN 128
#define BK 16

// ---------------- scratch (no allocation allowed) ----------------
__device__ float g_ht[BATCH * DIM];               // 32x1024
__device__ float g_spart[NCHUNKS * M_TOT];        // 8x65536 partial scores
__device__ float g_wpart[16 * BATCH * DIM];       // 16 l-splits of weighted

// ---------------- Kernel A: ht_proj[b][k] = sum_d x[b][d] * Wa[k][d] ----------------
// grid 8 blocks x 128 threads; each thread owns one k column for all 32 b.
__global__ void __launch_bounds__(128) ht_kernel(const float* __restrict__ x,
                                                 const float* __restrict__ Wa) {
    int k = blockIdx.x * 128 + threadIdx.x;   // 0..1023
    __shared__ float xs[32][128];
    float acc[32];
#pragma unroll
    for (int b = 0; b < 32; b++) acc[b] = 0.f;

    for (int d0 = 0; d0 < DIM; d0 += 128) {
        for (int i = threadIdx.x; i < 32 * 128; i += 128) {
            int bb = i >> 7, dd = i & 127;
            xs[bb][dd] = x[bb * DIM + d0 + dd];
        }
        __syncthreads();
        const float* wrow = Wa + (size_t)k * (2 * DIM) + d0;
#pragma unroll 4
        for (int dd = 0; dd < 128; dd++) {
            float w = wrow[dd];
#pragma unroll
            for (int b = 0; b < 32; b++) acc[b] += xs[b][dd] * w;
        }
        __syncthreads();
    }
#pragma unroll
    for (int b = 0; b < 32; b++) g_ht[b * DIM + k] = acc[b];
}

// ---------------- Kernel B: fused hs_proj GEMM + tanh + Va dot ----------------
// C[m][n] = sum_d ctx[m][d] * Wa_s[n][d]   (both K-major -> A*B^T)
// then score_part[nchunk][m] = sum_{n in chunk} Va[n] * tanh(C[m][n] + ht[b][n])
__global__ void __launch_bounds__(256) score_kernel(const float* __restrict__ ctx,
                                                    const float* __restrict__ Wa,
                                                    const float* __restrict__ Va) {
    const int nch = blockIdx.x;            // 0..7
    const int m0  = blockIdx.y * BM;       // row tile start (b*2048+l space)
    const int n0  = nch * BN;
    const int b   = m0 >> 11;              // m0 / 2048 (BM divides 2048)

    const int tid = threadIdx.x;
    const int tx  = tid & 15;              // col group
    const int ty  = tid >> 4;              // row group

    __shared__ float As[BK][BM];
    __shared__ float Bs[BK][BN];

    float c[8][8];
#pragma unroll
    for (int i = 0; i < 8; i++)
#pragma unroll
        for (int j = 0; j < 8; j++) c[i][j] = 0.f;

    const int lr = tid >> 2;               // 0..63
    const int lc = (tid & 3) * 4;          // 0,4,8,12

    const float* Abase = ctx + (size_t)m0 * DIM;
    const float* Bbase = Wa + DIM;         // Wa_s starts at column DIM; row stride 2*DIM

    for (int k0 = 0; k0 < DIM; k0 += BK) {
#pragma unroll
        for (int r = 0; r < 2; r++) {
            int row = lr + r * 64;
            float4 va = *(const float4*)(Abase + (size_t)row * DIM + k0 + lc);
            As[lc + 0][row] = va.x; As[lc + 1][row] = va.y;
            As[lc + 2][row] = va.z; As[lc + 3][row] = va.w;
            float4 vb = *(const float4*)(Bbase + (size_t)(n0 + row) * (2 * DIM) + k0 + lc);
            Bs[lc + 0][row] = vb.x; Bs[lc + 1][row] = vb.y;
            Bs[lc + 2][row] = vb.z; Bs[lc + 3][row] = vb.w;
        }
        __syncthreads();
#pragma unroll
        for (int kk = 0; kk < BK; kk++) {
            float a[8], bb[8];
            float4 a0 = *(const float4*)&As[kk][ty * 8];
            float4 a1 = *(const float4*)&As[kk][ty * 8 + 4];
            a[0]=a0.x; a[1]=a0.y; a[2]=a0.z; a[3]=a0.w;
            a[4]=a1.x; a[5]=a1.y; a[6]=a1.z; a[7]=a1.w;
            float4 b0 = *(const float4*)&Bs[kk][tx * 8];
            float4 b1 = *(const float4*)&Bs[kk][tx * 8 + 4];
            bb[0]=b0.x; bb[1]=b0.y; bb[2]=b0.z; bb[3]=b0.w;
            bb[4]=b1.x; bb[5]=b1.y; bb[6]=b1.z; bb[7]=b1.w;
#pragma unroll
            for (int i = 0; i < 8; i++)
#pragma unroll
                for (int j = 0; j < 8; j++) c[i][j] += a[i] * bb[j];
        }
        __syncthreads();
    }

    // epilogue: tanh + Va weighting, reduce over the 128 n's of this chunk
    float htr[8], va[8];
#pragma unroll
    for (int j = 0; j < 8; j++) {
        int n = n0 + tx * 8 + j;
        htr[j] = g_ht[b * DIM + n];
        va[j]  = Va[n];
    }
    float partial[8];
#pragma unroll
    for (int i = 0; i < 8; i++) {
        float s = 0.f;
#pragma unroll
        for (int j = 0; j < 8; j++) {
            float h = tanhf(c[i][j] + htr[j]);
            s += va[j] * h;
        }
        partial[i] = s;
    }

    __shared__ float red[BM][17];
#pragma unroll
    for (int i = 0; i < 8; i++) red[ty * 8 + i][tx] = partial[i];
    __syncthreads();
    if (tid < BM) {
        float s = 0.f;
#pragma unroll
        for (int t = 0; t < 16; t++) s += red[tid][t];
        g_spart[nch * M_TOT + m0 + tid] = s;
    }
}

// ---------------- Kernel C: sum partials + softmax over L, write attn ----------------
__global__ void __launch_bounds__(256) softmax_kernel(float* __restrict__ out) {
    int b = blockIdx.x;
    int tid = threadIdx.x;
    float v[8];
    float mx = -1e30f;
#pragma unroll
    for (int i = 0; i < 8; i++) {
        int l = i * 256 + tid;
        float s = 0.f;
#pragma unroll
        for (int c = 0; c < NCHUNKS; c++) s += g_spart[c * M_TOT + b * LEN + l];
        v[i] = s;
        mx = fmaxf(mx, s);
    }
    __shared__ float sm[256];
    sm[tid] = mx; __syncthreads();
    for (int off = 128; off > 0; off >>= 1) {
        if (tid < off) sm[tid] = fmaxf(sm[tid], sm[tid + off]);
        __syncthreads();
    }
    mx = sm[0];
    __syncthreads();
    float lsum = 0.f;
#pragma unroll
    for (int i = 0; i < 8; i++) { v[i] = expf(v[i] - mx); lsum += v[i]; }
    sm[tid] = lsum; __syncthreads();
    for (int off = 128; off > 0; off >>= 1) {
        if (tid < off) sm[tid] += sm[tid + off];
        __syncthreads();
    }
    float inv = 1.f / sm[0];
#pragma unroll
    for (int i = 0; i < 8; i++)
        out[BATCH * DIM + b * LEN + i * 256 + tid] = v[i] * inv;
}

// ---------------- Kernel D: partial weighted sums over l-chunks ----------------
// grid (16 l-splits, 32 b); 256 threads, each owns 4 d's (float4)
__global__ void __launch_bounds__(256) wpart_kernel(const float* __restrict__ ctx,
                                                    const float* __restrict__ out) {
    int ls = blockIdx.x;
    int b  = blockIdx.y;
    int tid = threadIdx.x;
    const float* attn = out + BATCH * DIM + b * LEN + ls * 128;
    const float* cp   = ctx + ((size_t)b * LEN + ls * 128) * DIM + tid * 4;
    float4 acc = make_float4(0.f, 0.f, 0.f, 0.f);
    for (int l = 0; l < 128; l++) {
        float a = attn[l];
        float4 v = *(const float4*)(cp + (size_t)l * DIM);
        acc.x += a * v.x; acc.y += a * v.y;
        acc.z += a * v.z; acc.w += a * v.w;
    }
    *(float4*)(g_wpart + ((size_t)ls * BATCH + b) * DIM + tid * 4) = acc;
}

// ---------------- Kernel E: reduce weighted partials ----------------
__global__ void __launch_bounds__(256) wreduce_kernel(float* __restrict__ out) {
    int i = blockIdx.x * 256 + threadIdx.x;   // 0..32767
    float s = 0.f;
#pragma unroll
    for (int ls = 0; ls < 16; ls++) s += g_wpart[ls * (BATCH * DIM) + i];
    out[i] = s;
}

// ---------------- launch ----------------
extern "C" void kernel_launch(void* const* d_in, const int* in_sizes, int n_in,
                              void* d_out, int out_size) {
    const float* x   = (const float*)d_in[0];   // 32*1024
    const float* ctx = (const float*)d_in[1];   // 32*2048*1024
    const float* Wa  = (const float*)d_in[2];   // 1024*2048
    const float* Va  = (const float*)d_in[3];   // 1024
    float* out = (float*)d_out;                 // [weighted 32*1024][attn 32*2048]

    ht_kernel<<<8, 128>>>(x, Wa);
    score_kernel<<<dim3(NCHUNKS, M_TOT / BM), 256>>>(ctx, Wa, Va);
    softmax_kernel<<<BATCH, 256>>>(out);
    wpart_kernel<<<dim3(16, BATCH), 256>>>(ctx, out);
    wreduce_kernel<<<BATCH * DIM / 256, 256>>>(out);
}

// round 4
// speedup vs baseline: 2.4112x; 2.4112x over previous
#include <cuda_runtime.h>
#include <cuda_bf16.h>
#include <math.h>
#include <stdint.h>

#define BATCH 32
#define LEN   2048
#define DIM   1024
#define M_TOT (BATCH * LEN)      // 65536
#define NCHUNKS 8

// ---------------- scratch (static, no allocation) ----------------
__device__ float g_ht[BATCH * DIM];
__device__ float g_spart[NCHUNKS * M_TOT];
__device__ float g_wpart[16 * BATCH * DIM];
// Split-precision B operand: [split][n][k] bf16, B[n][k] = Wa[n][1024+k]
__device__ __nv_bfloat16 g_B[2][DIM][DIM];

// ---------------- helpers ----------------
__device__ __forceinline__ uint32_t smem_u32(const void* p) {
    uint32_t a;
    asm("{ .reg .u64 t; cvta.to.shared.u64 t, %1; cvt.u32.u64 %0, t; }" : "=r"(a) : "l"(p));
    return a;
}

#define LDSM4(r, addr) \
    asm volatile("ldmatrix.sync.aligned.m8n8.x4.shared.b16 {%0,%1,%2,%3}, [%4];" \
        : "=r"((r)[0]), "=r"((r)[1]), "=r"((r)[2]), "=r"((r)[3]) : "r"(addr))

#define MMA16816(c, a, b0, b1) \
    asm volatile("mma.sync.aligned.m16n8k16.row.col.f32.bf16.bf16.f32 " \
        "{%0,%1,%2,%3}, {%4,%5,%6,%7}, {%8,%9}, {%0,%1,%2,%3};" \
        : "+f"((c)[0]), "+f"((c)[1]), "+f"((c)[2]), "+f"((c)[3]) \
        : "r"((a)[0]), "r"((a)[1]), "r"((a)[2]), "r"((a)[3]), "r"(b0), "r"(b1))

__device__ __forceinline__ uint32_t pack2bf(float v0, float v1) {
    uint32_t r;
    asm("cvt.rn.bf16x2.f32 %0, %1, %2;" : "=r"(r) : "f"(v1), "f"(v0));  // v0 -> low half
    return r;
}

// ---------------- Kernel A: ht_proj[b][k] = sum_d x[b][d] * Wa[k][d] ----------------
__global__ void __launch_bounds__(128) ht_kernel(const float* __restrict__ x,
                                                 const float* __restrict__ Wa) {
    int k = blockIdx.x * 128 + threadIdx.x;
    __shared__ float xs[32][128];
    float acc[32];
#pragma unroll
    for (int b = 0; b < 32; b++) acc[b] = 0.f;
    for (int d0 = 0; d0 < DIM; d0 += 128) {
        for (int i = threadIdx.x; i < 32 * 128; i += 128) {
            int bb = i >> 7, dd = i & 127;
            xs[bb][dd] = x[bb * DIM + d0 + dd];
        }
        __syncthreads();
        const float* wrow = Wa + (size_t)k * (2 * DIM) + d0;
#pragma unroll 4
        for (int dd = 0; dd < 128; dd++) {
            float w = wrow[dd];
#pragma unroll
            for (int b = 0; b < 32; b++) acc[b] += xs[b][dd] * w;
        }
        __syncthreads();
    }
#pragma unroll
    for (int b = 0; b < 32; b++) g_ht[b * DIM + k] = acc[b];
}

// ---------------- Kernel B0: split Wa_s -> g_B ----------------
// g_B[s][n][k] = Wa[n][1024 + k]  (row n of Wa, second-half columns; coalesced)
__global__ void __launch_bounds__(256) bprep_kernel(const float* __restrict__ Wa) {
    int idx = blockIdx.x * 256 + threadIdx.x;   // 524288 total
    int kp = idx & 511;                          // k pair index
    int n  = idx >> 9;                           // 0..1023
    float v0 = Wa[(size_t)n * 2048 + 1024 + 2 * kp];
    float v1 = Wa[(size_t)n * 2048 + 1024 + 2 * kp + 1];
    uint32_t ph = pack2bf(v0, v1);
    float h0 = __uint_as_float(ph << 16);
    float h1 = __uint_as_float(ph & 0xffff0000u);
    uint32_t pl = pack2bf(v0 - h0, v1 - h1);
    uint32_t* B32 = (uint32_t*)g_B;
    B32[(size_t)0 * 524288 + n * 512 + kp] = ph;
    B32[(size_t)1 * 524288 + n * 512 + kp] = pl;
}

// ---------------- Kernel B: mma.sync bf16x3 score GEMM + tanh + Va ----------------
// CTA: M=128 (blockIdx.y), N=128 (blockIdx.x), K=1024 in 32 steps of 32.
#define RS      80          // padded smem row stride (bytes) for 32 bf16
#define OFF_AH  0
#define OFF_AL  10240
#define OFF_BH  20480
#define OFF_BL  30720
#define BUF_SZ  40960
#define SM_HT   81920
#define SM_VA   82432
#define SM_RED  82944
#define SM_TOTAL 84992

__global__ void __launch_bounds__(256, 1) score_kernel(const float* __restrict__ ctx,
                                                       const float* __restrict__ Va) {
    extern __shared__ char smem[];
    const uint32_t sb = smem_u32(smem);
    const int tid  = threadIdx.x;
    const int lane = tid & 31;
    const int wid  = tid >> 5;
    const int wm   = wid >> 2;        // 0..1 (64 rows each)
    const int wn   = wid & 3;         // 0..3 (32 cols each)
    const int nch  = blockIdx.x;
    const int m0   = blockIdx.y * 128;
    const int n0   = nch * 128;
    const int b    = blockIdx.y >> 4;

    float* sht = (float*)(smem + SM_HT);
    float* sva = (float*)(smem + SM_VA);
    if (tid < 128) {
        sht[tid] = g_ht[b * DIM + n0 + tid];
        sva[tid] = Va[n0 + tid];
    }

    float acc[4][4][4];
#pragma unroll
    for (int i = 0; i < 4; i++)
#pragma unroll
        for (int j = 0; j < 4; j++)
#pragma unroll
            for (int r = 0; r < 4; r++) acc[i][j][r] = 0.f;

    // ---- gmem prefetch regs ----
    float4 ra[4];
    uint4  rb[2][2];
    const int t8 = tid & 7, rA0 = tid >> 3;      // A: 8 threads/row
    const int c4 = tid & 3, rB0 = tid >> 2;      // B: 4 threads/row
    const uint32_t* B32 = (const uint32_t*)g_B;

#define LDG_TILES(kc_) do { \
    const float* ap = ctx + (size_t)(m0 + rA0) * DIM + (kc_) * 32 + t8 * 4; \
    _Pragma("unroll") \
    for (int rr = 0; rr < 4; rr++) ra[rr] = *(const float4*)(ap + (size_t)rr * 32 * DIM); \
    _Pragma("unroll") \
    for (int s = 0; s < 2; s++) \
    _Pragma("unroll") \
    for (int rr = 0; rr < 2; rr++) \
        rb[s][rr] = *(const uint4*)(B32 + (size_t)s * 524288 + (size_t)(n0 + rB0 + rr * 64) * 512 + (kc_) * 16 + c4 * 4); \
} while (0)

#define STS_TILES(bufc_) do { \
    char* bp_ = smem + (bufc_) * BUF_SZ; \
    _Pragma("unroll") \
    for (int rr = 0; rr < 4; rr++) { \
        float4 v = ra[rr]; \
        uint32_t p0 = pack2bf(v.x, v.y); \
        float h0 = __uint_as_float(p0 << 16), h1 = __uint_as_float(p0 & 0xffff0000u); \
        uint32_t l0 = pack2bf(v.x - h0, v.y - h1); \
        uint32_t p1 = pack2bf(v.z, v.w); \
        float h2 = __uint_as_float(p1 << 16), h3 = __uint_as_float(p1 & 0xffff0000u); \
        uint32_t l1 = pack2bf(v.z - h2, v.w - h3); \
        int row = rA0 + rr * 32; \
        *(uint2*)(bp_ + OFF_AH + row * RS + t8 * 8) = make_uint2(p0, p1); \
        *(uint2*)(bp_ + OFF_AL + row * RS + t8 * 8) = make_uint2(l0, l1); \
    } \
    _Pragma("unroll") \
    for (int rr = 0; rr < 2; rr++) { \
        int row = rB0 + rr * 64; \
        *(uint4*)(bp_ + OFF_BH + row * RS + c4 * 16) = rb[0][rr]; \
        *(uint4*)(bp_ + OFF_BL + row * RS + c4 * 16) = rb[1][rr]; \
    } \
} while (0)

    // ldmatrix per-thread address components
    const uint32_t aoff = (uint32_t)((wm * 64 + (lane & 15)) * RS + (lane >> 4) * 16);
    const uint32_t boff = (uint32_t)((wn * 32 + (lane & 7) + ((lane >> 4) & 1) * 8) * RS
                                     + ((lane >> 3) & 1) * 16);

    LDG_TILES(0);
    STS_TILES(0);
    __syncthreads();

#pragma unroll 1
    for (int kc = 0; kc < 32; kc++) {
        if (kc < 31) LDG_TILES(kc + 1);

        const uint32_t bufb = sb + (uint32_t)(kc & 1) * BUF_SZ;
        const uint32_t aAh = bufb + OFF_AH + aoff;
        const uint32_t aAl = bufb + OFF_AL + aoff;
        const uint32_t aBh = bufb + OFF_BH + boff;
        const uint32_t aBl = bufb + OFF_BL + boff;

#pragma unroll
        for (int ks = 0; ks < 2; ks++) {
            uint32_t ah[4][4], al[4][4], bh[2][4], bl[2][4];
#pragma unroll
            for (int mt = 0; mt < 4; mt++) {
                LDSM4(ah[mt], aAh + mt * (16 * RS) + ks * 32);
                LDSM4(al[mt], aAl + mt * (16 * RS) + ks * 32);
            }
#pragma unroll
            for (int p = 0; p < 2; p++) {
                LDSM4(bh[p], aBh + p * (16 * RS) + ks * 32);
                LDSM4(bl[p], aBl + p * (16 * RS) + ks * 32);
            }
#pragma unroll
            for (int mt = 0; mt < 4; mt++)
#pragma unroll
                for (int nt = 0; nt < 4; nt++) {
                    uint32_t* bhp = &bh[nt >> 1][(nt & 1) * 2];
                    uint32_t* blp = &bl[nt >> 1][(nt & 1) * 2];
                    MMA16816(acc[mt][nt], ah[mt], bhp[0], bhp[1]);
                    MMA16816(acc[mt][nt], ah[mt], blp[0], blp[1]);
                    MMA16816(acc[mt][nt], al[mt], bhp[0], bhp[1]);
                }
        }
        if (kc < 31) STS_TILES((kc + 1) & 1);
        __syncthreads();
    }

    // ---- epilogue: tanh(D + ht) * Va, reduce over n ----
    float* red = (float*)(smem + SM_RED);   // [128][4]
    const int quad = lane >> 2, qlane = lane & 3;
#pragma unroll
    for (int mt = 0; mt < 4; mt++) {
#pragma unroll
        for (int h = 0; h < 2; h++) {
            float s = 0.f;
#pragma unroll
            for (int nt = 0; nt < 4; nt++) {
#pragma unroll
                for (int j = 0; j < 2; j++) {
                    int c = wn * 32 + nt * 8 + qlane * 2 + j;
                    float d = acc[mt][nt][h * 2 + j];
                    s += sva[c] * tanhf(d + sht[c]);
                }
            }
            s += __shfl_xor_sync(0xffffffffu, s, 1);
            s += __shfl_xor_sync(0xffffffffu, s, 2);
            if (qlane == 0) {
                int row = wm * 64 + mt * 16 + quad + h * 8;
                red[row * 4 + wn] = s;
            }
        }
    }
    __syncthreads();
    if (tid < 128) {
        float s = red[tid * 4] + red[tid * 4 + 1] + red[tid * 4 + 2] + red[tid * 4 + 3];
        g_spart[(size_t)nch * M_TOT + m0 + tid] = s;
    }
}

// ---------------- Kernel C: sum partials + softmax ----------------
__global__ void __launch_bounds__(256) softmax_kernel(float* __restrict__ out) {
    int b = blockIdx.x;
    int tid = threadIdx.x;
    float v[8];
    float mx = -1e30f;
#pragma unroll
    for (int i = 0; i < 8; i++) {
        int l = i * 256 + tid;
        float s = 0.f;
#pragma unroll
        for (int c = 0; c < NCHUNKS; c++) s += g_spart[(size_t)c * M_TOT + b * LEN + l];
        v[i] = s;
        mx = fmaxf(mx, s);
    }
    __shared__ float sm[256];
    sm[tid] = mx; __syncthreads();
    for (int off = 128; off > 0; off >>= 1) {
        if (tid < off) sm[tid] = fmaxf(sm[tid], sm[tid + off]);
        __syncthreads();
    }
    mx = sm[0];
    __syncthreads();
    float lsum = 0.f;
#pragma unroll
    for (int i = 0; i < 8; i++) { v[i] = expf(v[i] - mx); lsum += v[i]; }
    sm[tid] = lsum; __syncthreads();
    for (int off = 128; off > 0; off >>= 1) {
        if (tid < off) sm[tid] += sm[tid + off];
        __syncthreads();
    }
    float inv = 1.f / sm[0];
#pragma unroll
    for (int i = 0; i < 8; i++)
        out[BATCH * DIM + b * LEN + i * 256 + tid] = v[i] * inv;
}

// ---------------- Kernel D: partial weighted sums ----------------
__global__ void __launch_bounds__(256) wpart_kernel(const float* __restrict__ ctx,
                                                    const float* __restrict__ out) {
    int ls = blockIdx.x;
    int b  = blockIdx.y;
    int tid = threadIdx.x;
    const float* attn = out + BATCH * DIM + b * LEN + ls * 128;
    const float* cp   = ctx + ((size_t)b * LEN + ls * 128) * DIM + tid * 4;
    float4 acc = make_float4(0.f, 0.f, 0.f, 0.f);
    for (int l = 0; l < 128; l++) {
        float a = attn[l];
        float4 v = *(const float4*)(cp + (size_t)l * DIM);
        acc.x += a * v.x; acc.y += a * v.y;
        acc.z += a * v.z; acc.w += a * v.w;
    }
    *(float4*)(g_wpart + ((size_t)ls * BATCH + b) * DIM + tid * 4) = acc;
}

// ---------------- Kernel E: reduce weighted partials ----------------
__global__ void __launch_bounds__(256) wreduce_kernel(float* __restrict__ out) {
    int i = blockIdx.x * 256 + threadIdx.x;
    float s = 0.f;
#pragma unroll
    for (int ls = 0; ls < 16; ls++) s += g_wpart[ls * (BATCH * DIM) + i];
    out[i] = s;
}

// ---------------- launch ----------------
extern "C" void kernel_launch(void* const* d_in, const int* in_sizes, int n_in,
                              void* d_out, int out_size) {
    const float* x   = (const float*)d_in[0];
    const float* ctx = (const float*)d_in[1];
    const float* Wa  = (const float*)d_in[2];
    const float* Va  = (const float*)d_in[3];
    float* out = (float*)d_out;

    cudaFuncSetAttribute(score_kernel, cudaFuncAttributeMaxDynamicSharedMemorySize, SM_TOTAL);

    ht_kernel<<<8, 128>>>(x, Wa);
    bprep_kernel<<<2048, 256>>>(Wa);
    score_kernel<<<dim3(NCHUNKS, 512), 256, SM_TOTAL>>>(ctx, Va);
    softmax_kernel<<<BATCH, 256>>>(out);
    wpart_kernel<<<dim3(16, BATCH), 256>>>(ctx, out);
    wreduce_kernel<<<BATCH * DIM / 256, 256>>>(out);
}